// round 2
// baseline (speedup 1.0000x reference)
#include <cuda_runtime.h>
#include <math.h>

#define B_    4
#define T_    1000
#define C_    1024
#define H_    16
#define D_    64
#define M_TOK (B_*T_)   // 4000

typedef unsigned long long u64;

// Scratch (allocation-free: device globals)
__device__ float g_q[B_*H_*T_*D_];
__device__ float g_k[B_*H_*T_*D_];
__device__ float g_v[B_*H_*T_*D_];
__device__ float g_y[M_TOK*C_];
__device__ float g_cos[T_*(D_/2)];
__device__ float g_sin[T_*(D_/2)];

// ---------------------------------------------------------------------------
// packed f32x2 helpers (FFMA2 path — ptxas never emits these from plain C++)
// ---------------------------------------------------------------------------
__device__ __forceinline__ u64 fma2(u64 a, u64 b, u64 c) {
    u64 d;
    asm("fma.rn.f32x2 %0, %1, %2, %3;" : "=l"(d) : "l"(a), "l"(b), "l"(c));
    return d;
}
__device__ __forceinline__ u64 mul2(u64 a, u64 b) {
    u64 d;
    asm("mul.rn.f32x2 %0, %1, %2;" : "=l"(d) : "l"(a), "l"(b));
    return d;
}
__device__ __forceinline__ u64 pack2(float x, float y) {
    u64 d;
    asm("mov.b64 %0, {%1, %2};" : "=l"(d) : "r"(__float_as_uint(x)), "r"(__float_as_uint(y)));
    return d;
}
__device__ __forceinline__ void unpack2(u64 v, float& x, float& y) {
    unsigned a, b;
    asm("mov.b64 {%0, %1}, %2;" : "=r"(a), "=r"(b) : "l"(v));
    x = __uint_as_float(a);
    y = __uint_as_float(b);
}

// ---------------------------------------------------------------------------
// RoPE cos/sin table (matches reference fp32 math)
// ---------------------------------------------------------------------------
__global__ void rope_table_kernel() {
    int t = blockIdx.x;
    int i = threadIdx.x;     // pair index, d = 2*i
    float theta = (float)pow(10000.0, -(double)(2 * i) / 64.0);
    float ang = (float)t * theta;
    g_cos[t * 32 + i] = cosf(ang);
    g_sin[t * 32 + i] = sinf(ang);
}

// ---------------------------------------------------------------------------
// 128x128x8 fp32 SGEMM, 256 threads, 8x8 per thread, FFMA2 micro-kernel.
// Accumulators packed along j (column pairs): accp[8][4].
// MODE 0: C = x @ W_attn, epilogue scatters Q/K/V with fused RoPE.
// MODE 1: C = g_y @ W_proj, plain row-major write.
// ---------------------------------------------------------------------------
template<int MODE>
__global__ void __launch_bounds__(256)
gemm128(const float* __restrict__ Ain, const float* __restrict__ Bw,
        float* __restrict__ Cout, int M, int N, int K)
{
    const float* A = (MODE == 1) ? (const float*)g_y : Ain;

    __shared__ float As[8][128];   // transposed A tile
    __shared__ float Bs[8][128];

    int tid = threadIdx.x;
    int bm = blockIdx.y * 128;
    int bn = blockIdx.x * 128;
    int ty = tid >> 4;        // 0..15
    int tx = tid & 15;        // 0..15

    u64 accp[8][4];
#pragma unroll
    for (int i = 0; i < 8; i++)
#pragma unroll
        for (int j = 0; j < 4; j++) accp[i][j] = 0ULL;

    int arow  = tid >> 1;          // 0..127
    int acol4 = (tid & 1) * 4;     // 0 or 4
    int brow  = tid >> 5;          // 0..7
    int bcol  = (tid & 31) * 4;    // 0..124

    for (int k0 = 0; k0 < K; k0 += 8) {
        float4 av = make_float4(0.f, 0.f, 0.f, 0.f);
        if (bm + arow < M)
            av = *(const float4*)(A + (size_t)(bm + arow) * K + k0 + acol4);
        As[acol4 + 0][arow] = av.x;
        As[acol4 + 1][arow] = av.y;
        As[acol4 + 2][arow] = av.z;
        As[acol4 + 3][arow] = av.w;

        *(float4*)&Bs[brow][bcol] =
            *(const float4*)(Bw + (size_t)(k0 + brow) * N + bn + bcol);

        __syncthreads();

#pragma unroll
        for (int kk = 0; kk < 8; kk++) {
            float4 a0 = *(const float4*)&As[kk][ty * 8];
            float4 a1 = *(const float4*)&As[kk][ty * 8 + 4];
            ulonglong2 bq0 = *(const ulonglong2*)&Bs[kk][tx * 8];
            ulonglong2 bq1 = *(const ulonglong2*)&Bs[kk][tx * 8 + 4];
            u64 rb[4] = { bq0.x, bq0.y, bq1.x, bq1.y };
            u64 aa[8];
            aa[0] = pack2(a0.x, a0.x); aa[1] = pack2(a0.y, a0.y);
            aa[2] = pack2(a0.z, a0.z); aa[3] = pack2(a0.w, a0.w);
            aa[4] = pack2(a1.x, a1.x); aa[5] = pack2(a1.y, a1.y);
            aa[6] = pack2(a1.z, a1.z); aa[7] = pack2(a1.w, a1.w);
#pragma unroll
            for (int i = 0; i < 8; i++)
#pragma unroll
                for (int j = 0; j < 4; j++)
                    accp[i][j] = fma2(aa[i], rb[j], accp[i][j]);
        }
        __syncthreads();
    }

    if (MODE == 1) {
#pragma unroll
        for (int i = 0; i < 8; i++) {
            int gr = bm + ty * 8 + i;
            if (gr >= M) continue;
            float xo[8];
#pragma unroll
            for (int j = 0; j < 4; j++) unpack2(accp[i][j], xo[2*j], xo[2*j+1]);
            float* dst = Cout + (size_t)gr * N + bn + tx * 8;
            *(float4*)dst       = make_float4(xo[0], xo[1], xo[2], xo[3]);
            *(float4*)(dst + 4) = make_float4(xo[4], xo[5], xo[6], xo[7]);
        }
    } else {
        // 8 consecutive columns live inside a single head (64-aligned groups)
        int c0    = bn + tx * 8;
        int which = c0 >> 10;            // 0=Q, 1=K, 2=V
        int h     = (c0 & 1023) >> 6;
        int dbase = c0 & 63;
#pragma unroll
        for (int i = 0; i < 8; i++) {
            int gr = bm + ty * 8 + i;
            if (gr >= M) continue;
            int b = gr / T_;
            int t = gr - b * T_;
            size_t base = ((size_t)(b * H_ + h) * T_ + t) * D_ + dbase;
            float xo[8];
#pragma unroll
            for (int j = 0; j < 4; j++) unpack2(accp[i][j], xo[2*j], xo[2*j+1]);
            if (which == 2) {
                *(float4*)&g_v[base]     = make_float4(xo[0], xo[1], xo[2], xo[3]);
                *(float4*)&g_v[base + 4] = make_float4(xo[4], xo[5], xo[6], xo[7]);
            } else {
                float* dst = (which == 0 ? g_q : g_k) + base;
#pragma unroll
                for (int p = 0; p < 4; p++) {
                    int pi = (dbase >> 1) + p;   // column pair == RoPE pair
                    float ct = g_cos[t * 32 + pi];
                    float st = g_sin[t * 32 + pi];
                    float x0 = xo[2*p], x1 = xo[2*p+1];
                    dst[2 * p]     = x0 * ct - x1 * st;
                    dst[2 * p + 1] = x1 * ct + x0 * st;
                }
            }
        }
    }
}

// ---------------------------------------------------------------------------
// Flash-style causal attention with f32x2 inner loops.
// Grid: (qtiles=16, H, B), 64 threads; each thread owns one q row.
// ---------------------------------------------------------------------------
__global__ void __launch_bounds__(64) attn_kernel() {
    int qt = gridDim.x - 1 - blockIdx.x;   // heavy tiles first
    int h  = blockIdx.y;
    int b  = blockIdx.z;
    int r  = threadIdx.x;
    int qrow = qt * 64 + r;
    bool active = (qrow < T_);

    __shared__ float Ks[32][64];
    __shared__ float Vs[32][64];
    __shared__ float Sb[32][64];           // [k-col][q-row]

    const float scale = 0.125f;            // 1/sqrt(64)

    u64 qp[32], op[32];                    // pairs along d
#pragma unroll
    for (int d2 = 0; d2 < 32; d2++) op[d2] = 0ULL;

    {
        size_t qoff = ((size_t)(b * H_ + h) * T_ + (active ? qrow : 0)) * D_;
#pragma unroll
        for (int d = 0; d < 64; d += 4) {
            float4 v = *(const float4*)&g_q[qoff + d];
            qp[d / 2]     = pack2(v.x * scale, v.y * scale);
            qp[d / 2 + 1] = pack2(v.z * scale, v.w * scale);
        }
    }

    float m = -1e30f, l = 0.f;
    int maxq = min(qt * 64 + 63, T_ - 1);
    int nkt  = maxq / 32 + 1;
    size_t kvbase = (size_t)(b * H_ + h) * T_ * D_;

    for (int kt = 0; kt < nkt; kt++) {
        int kbase = kt * 32;

#pragma unroll
        for (int u = 0; u < 8; u++) {
            int e4 = u * 64 + r;            // float4 index 0..511
            int j  = e4 >> 4;
            int d  = (e4 & 15) * 4;
            int kg = kbase + j;
            float4 kv = make_float4(0.f, 0.f, 0.f, 0.f);
            float4 vv = make_float4(0.f, 0.f, 0.f, 0.f);
            if (kg < T_) {
                kv = *(const float4*)&g_k[kvbase + (size_t)kg * D_ + d];
                vv = *(const float4*)&g_v[kvbase + (size_t)kg * D_ + d];
            }
            *(float4*)&Ks[j][d] = kv;
            *(float4*)&Vs[j][d] = vv;
        }
        __syncthreads();

        if (active) {
            // pass 1: scores (pairwise over d) + tile max
            float tmax = -1e30f;
#pragma unroll 1
            for (int j0 = 0; j0 < 32; j0 += 4) {
                u64 s0 = 0ULL, s1 = 0ULL, s2 = 0ULL, s3 = 0ULL;
                const u64* k0p = (const u64*)&Ks[j0 + 0][0];
                const u64* k1p = (const u64*)&Ks[j0 + 1][0];
                const u64* k2p = (const u64*)&Ks[j0 + 2][0];
                const u64* k3p = (const u64*)&Ks[j0 + 3][0];
#pragma unroll
                for (int d2 = 0; d2 < 32; d2++) {
                    u64 qd = qp[d2];
                    s0 = fma2(qd, k0p[d2], s0);
                    s1 = fma2(qd, k1p[d2], s1);
                    s2 = fma2(qd, k2p[d2], s2);
                    s3 = fma2(qd, k3p[d2], s3);
                }
                float a, bb, sc[4];
                unpack2(s0, a, bb); sc[0] = a + bb;
                unpack2(s1, a, bb); sc[1] = a + bb;
                unpack2(s2, a, bb); sc[2] = a + bb;
                unpack2(s3, a, bb); sc[3] = a + bb;
#pragma unroll
                for (int u = 0; u < 4; u++) {
                    int kg = kbase + j0 + u;
                    if (kg > qrow || kg >= T_) sc[u] = -1e30f;
                    Sb[j0 + u][r] = sc[u];
                }
                tmax = fmaxf(tmax, fmaxf(fmaxf(sc[0], sc[1]), fmaxf(sc[2], sc[3])));
            }

            // online softmax rescale (once per tile)
            float mnew = fmaxf(m, tmax);
            float f = __expf(m - mnew);
            l *= f;
            u64 ff = pack2(f, f);
#pragma unroll
            for (int d2 = 0; d2 < 32; d2++) op[d2] = mul2(op[d2], ff);

            // pass 2: probs + O accumulation (pairwise over d)
#pragma unroll 1
            for (int j = 0; j < 32; j++) {
                float p = __expf(Sb[j][r] - mnew);
                l += p;
                u64 pp = pack2(p, p);
                const u64* vp = (const u64*)&Vs[j][0];
#pragma unroll
                for (int d2 = 0; d2 < 32; d2++)
                    op[d2] = fma2(pp, vp[d2], op[d2]);
            }
            m = mnew;
        }
        __syncthreads();
    }

    if (active) {
        float inv = 1.f / l;
        float* yp = &g_y[((size_t)(b * T_) + qrow) * C_ + h * D_];
#pragma unroll
        for (int d = 0; d < 64; d += 4) {
            float x0, x1, x2, x3;
            unpack2(op[d / 2],     x0, x1);
            unpack2(op[d / 2 + 1], x2, x3);
            *(float4*)&yp[d] = make_float4(x0 * inv, x1 * inv, x2 * inv, x3 * inv);
        }
    }
}

// ---------------------------------------------------------------------------
extern "C" void kernel_launch(void* const* d_in, const int* in_sizes, int n_in,
                              void* d_out, int out_size)
{
    const float* x      = (const float*)d_in[0];
    const float* W_attn = (const float*)d_in[2];
    const float* W_proj = (const float*)d_in[3];
    float* out = (float*)d_out;

    rope_table_kernel<<<T_, 32>>>();

    dim3 g_qkv(3072 / 128, (M_TOK + 127) / 128);   // 24 x 32
    gemm128<0><<<g_qkv, 256>>>(x, W_attn, nullptr, M_TOK, 3072, 1024);

    dim3 g_attn((T_ + 63) / 64, H_, B_);           // 16 x 16 x 4
    attn_kernel<<<g_attn, 64>>>();

    dim3 g_proj(1024 / 128, (M_TOK + 127) / 128);  // 8 x 32
    gemm128<1><<<g_proj, 256>>>(nullptr, W_proj, out, M_TOK, 1024, 1024);
}

// round 3
// speedup vs baseline: 1.6241x; 1.6241x over previous
#include <cuda_runtime.h>
#include <math.h>
#include <stdint.h>

#define B_    4
#define T_    1000
#define C_    1024
#define H_    16
#define D_    64
#define M_TOK (B_*T_)   // 4000

// Scratch (allocation-free: device globals)
__device__ float g_q[B_*H_*T_*D_];
__device__ float g_k[B_*H_*T_*D_];
__device__ float g_v[B_*H_*T_*D_];
__device__ float g_y[M_TOK*C_];
__device__ float g_cos[T_*(D_/2)];
__device__ float g_sin[T_*(D_/2)];

// ---------------------------------------------------------------------------
// helpers
// ---------------------------------------------------------------------------
__device__ __forceinline__ uint32_t f2tf32(float x) {
    uint32_t u;
    asm("cvt.rna.tf32.f32 %0, %1;" : "=r"(u) : "f"(x));
    return u;
}

__device__ __forceinline__ void mma_tf32(float c[4],
                                         const uint32_t a[4],
                                         const uint32_t b[2]) {
    asm volatile(
        "mma.sync.aligned.m16n8k8.row.col.f32.tf32.tf32.f32 "
        "{%0,%1,%2,%3}, {%4,%5,%6,%7}, {%8,%9}, {%0,%1,%2,%3};"
        : "+f"(c[0]), "+f"(c[1]), "+f"(c[2]), "+f"(c[3])
        : "r"(a[0]), "r"(a[1]), "r"(a[2]), "r"(a[3]),
          "r"(b[0]), "r"(b[1]));
}

// ---------------------------------------------------------------------------
// RoPE cos/sin table (matches reference fp32 math)
// ---------------------------------------------------------------------------
__global__ void rope_table_kernel() {
    int t = blockIdx.x;
    int i = threadIdx.x;     // pair index, d = 2*i
    float theta = (float)pow(10000.0, -(double)(2 * i) / 64.0);
    float ang = (float)t * theta;
    g_cos[t * 32 + i] = cosf(ang);
    g_sin[t * 32 + i] = sinf(ang);
}

// ---------------------------------------------------------------------------
// 128x128 tf32 tensor-core GEMM. 256 threads = 8 warps (2m x 4n), each warp
// 64x32 via 4x4 m16n8k8 fragments. BK=16 (2 k-steps per chunk), register
// prefetch of the next global chunk. smem stride 136 -> conflict-free frags.
// MODE 0: C = x @ W_attn, epilogue fuses RoPE and scatters Q/K/V [B,H,T,D].
// MODE 1: C = g_y @ W_proj -> Cout row-major.
// ---------------------------------------------------------------------------
#define BK  16
#define LDS_ 136

template<int MODE>
__global__ void __launch_bounds__(256)
gemm_tc(const float* __restrict__ Ain, const float* __restrict__ Bw,
        float* __restrict__ Cout, int M, int N, int K)
{
    const float* A = (MODE == 1) ? (const float*)g_y : Ain;

    __shared__ uint32_t As[BK * LDS_];   // [k][m] transposed, tf32 bits
    __shared__ uint32_t Bs[BK * LDS_];   // [k][n], tf32 bits

    const int tid  = threadIdx.x;
    const int warp = tid >> 5;
    const int lane = tid & 31;
    const int g    = lane >> 2;     // 0..7
    const int tg   = lane & 3;      // 0..3
    const int wm   = warp >> 2;     // 0..1
    const int wn   = warp & 3;      // 0..3
    const int wmB  = wm * 64;
    const int wnB  = wn * 32;

    const int bm = blockIdx.y * 128;
    const int bn = blockIdx.x * 128;

    float acc[4][4][4];
#pragma unroll
    for (int mf = 0; mf < 4; mf++)
#pragma unroll
        for (int nf = 0; nf < 4; nf++)
#pragma unroll
            for (int i = 0; i < 4; i++) acc[mf][nf][i] = 0.f;

    // global load indexing (2 float4 each for A and B per chunk)
    const int aid0 = tid * 2;
    const int arow0 = aid0 >> 2,  akq0 = (aid0 & 3) * 4;
    const int arow1 = (aid0 + 1) >> 2, akq1 = ((aid0 + 1) & 3) * 4;
    const int brow0 = aid0 >> 5,  bc0  = (aid0 & 31) * 4;
    const int brow1 = (aid0 + 1) >> 5, bc1 = ((aid0 + 1) & 31) * 4;

    float4 pa0, pa1, pb0, pb1;

    // prologue: load chunk 0
    {
        pa0 = make_float4(0.f, 0.f, 0.f, 0.f);
        pa1 = pa0;
        if (bm + arow0 < M) pa0 = *(const float4*)(A + (size_t)(bm + arow0) * K + akq0);
        if (bm + arow1 < M) pa1 = *(const float4*)(A + (size_t)(bm + arow1) * K + akq1);
        pb0 = *(const float4*)(Bw + (size_t)brow0 * N + bn + bc0);
        pb1 = *(const float4*)(Bw + (size_t)brow1 * N + bn + bc1);
    }

    const int nchunk = K / BK;
    for (int ch = 0; ch < nchunk; ch++) {
        // store prefetched chunk to smem (with tf32 convert)
        As[(akq0 + 0) * LDS_ + arow0] = f2tf32(pa0.x);
        As[(akq0 + 1) * LDS_ + arow0] = f2tf32(pa0.y);
        As[(akq0 + 2) * LDS_ + arow0] = f2tf32(pa0.z);
        As[(akq0 + 3) * LDS_ + arow0] = f2tf32(pa0.w);
        As[(akq1 + 0) * LDS_ + arow1] = f2tf32(pa1.x);
        As[(akq1 + 1) * LDS_ + arow1] = f2tf32(pa1.y);
        As[(akq1 + 2) * LDS_ + arow1] = f2tf32(pa1.z);
        As[(akq1 + 3) * LDS_ + arow1] = f2tf32(pa1.w);
        {
            uint4 u0 = make_uint4(f2tf32(pb0.x), f2tf32(pb0.y), f2tf32(pb0.z), f2tf32(pb0.w));
            uint4 u1 = make_uint4(f2tf32(pb1.x), f2tf32(pb1.y), f2tf32(pb1.z), f2tf32(pb1.w));
            *(uint4*)&Bs[brow0 * LDS_ + bc0] = u0;
            *(uint4*)&Bs[brow1 * LDS_ + bc1] = u1;
        }
        __syncthreads();

        // prefetch next chunk
        if (ch + 1 < nchunk) {
            const int k0 = (ch + 1) * BK;
            pa0 = make_float4(0.f, 0.f, 0.f, 0.f);
            pa1 = pa0;
            if (bm + arow0 < M) pa0 = *(const float4*)(A + (size_t)(bm + arow0) * K + k0 + akq0);
            if (bm + arow1 < M) pa1 = *(const float4*)(A + (size_t)(bm + arow1) * K + k0 + akq1);
            pb0 = *(const float4*)(Bw + (size_t)(k0 + brow0) * N + bn + bc0);
            pb1 = *(const float4*)(Bw + (size_t)(k0 + brow1) * N + bn + bc1);
        }

        // compute 2 k-steps of 8
#pragma unroll
        for (int s = 0; s < 2; s++) {
            uint32_t afr[4][4], bfr[4][2];
            const int kr0 = (8 * s + tg) * LDS_;
            const int kr1 = (8 * s + tg + 4) * LDS_;
#pragma unroll
            for (int mf = 0; mf < 4; mf++) {
                int m0 = wmB + mf * 16 + g;
                afr[mf][0] = As[kr0 + m0];
                afr[mf][1] = As[kr0 + m0 + 8];
                afr[mf][2] = As[kr1 + m0];
                afr[mf][3] = As[kr1 + m0 + 8];
            }
#pragma unroll
            for (int nf = 0; nf < 4; nf++) {
                int n0 = wnB + nf * 8 + g;
                bfr[nf][0] = Bs[kr0 + n0];
                bfr[nf][1] = Bs[kr1 + n0];
            }
#pragma unroll
            for (int mf = 0; mf < 4; mf++)
#pragma unroll
                for (int nf = 0; nf < 4; nf++)
                    mma_tf32(acc[mf][nf], afr[mf], bfr[nf]);
        }
        __syncthreads();
    }

    // ---------------- epilogue ----------------
    if (MODE == 1) {
#pragma unroll
        for (int mf = 0; mf < 4; mf++) {
#pragma unroll
            for (int half = 0; half < 2; half++) {
                int gr = bm + wmB + mf * 16 + g + half * 8;
                if (gr >= M) continue;
#pragma unroll
                for (int nf = 0; nf < 4; nf++) {
                    int c = bn + wnB + nf * 8 + tg * 2;
                    *(float2*)&Cout[(size_t)gr * N + c] =
                        make_float2(acc[mf][nf][2 * half], acc[mf][nf][2 * half + 1]);
                }
            }
        }
    } else {
        // column group: which tensor / head constant per warp
        int cwarp = bn + wnB;            // 32-aligned
        int which = cwarp >> 10;         // 0=Q, 1=K, 2=V
        int h     = (cwarp & 1023) >> 6;
#pragma unroll
        for (int mf = 0; mf < 4; mf++) {
#pragma unroll
            for (int half = 0; half < 2; half++) {
                int gr = bm + wmB + mf * 16 + g + half * 8;
                if (gr >= M) continue;
                int b = gr / T_;
                int t = gr - b * T_;
                size_t rowbase = ((size_t)(b * H_ + h) * T_ + t) * D_;
#pragma unroll
                for (int nf = 0; nf < 4; nf++) {
                    int c     = bn + wnB + nf * 8 + tg * 2;
                    int dbase = c & 63;          // even
                    float x0 = acc[mf][nf][2 * half];
                    float x1 = acc[mf][nf][2 * half + 1];
                    if (which == 2) {
                        *(float2*)&g_v[rowbase + dbase] = make_float2(x0, x1);
                    } else {
                        int pi = dbase >> 1;
                        float ct = g_cos[t * 32 + pi];
                        float st = g_sin[t * 32 + pi];
                        float* dst = (which == 0 ? g_q : g_k) + rowbase + dbase;
                        *(float2*)dst = make_float2(x0 * ct - x1 * st,
                                                    x1 * ct + x0 * st);
                    }
                }
            }
        }
    }
}

// ---------------------------------------------------------------------------
// Flash-style causal attention (Round-1 scalar version — fastest so far).
// Grid: (qtiles=16, H, B), 64 threads; each thread owns one q row.
// ---------------------------------------------------------------------------
__global__ void __launch_bounds__(64) attn_kernel() {
    int qt = gridDim.x - 1 - blockIdx.x;   // heavy tiles first
    int h  = blockIdx.y;
    int b  = blockIdx.z;
    int r  = threadIdx.x;
    int qrow = qt * 64 + r;
    bool active = (qrow < T_);

    __shared__ float Ks[32][64];
    __shared__ float Vs[32][64];
    __shared__ float Sb[32][64];           // [k-col][q-row]

    const float scale = 0.125f;            // 1/sqrt(64)

    float q[64], o[64];
#pragma unroll
    for (int d = 0; d < 64; d++) o[d] = 0.f;

    {
        size_t qoff = ((size_t)(b * H_ + h) * T_ + (active ? qrow : 0)) * D_;
#pragma unroll
        for (int d = 0; d < 64; d += 4) {
            float4 v = *(const float4*)&g_q[qoff + d];
            q[d]     = v.x * scale;
            q[d + 1] = v.y * scale;
            q[d + 2] = v.z * scale;
            q[d + 3] = v.w * scale;
        }
    }

    float m = -1e30f, l = 0.f;
    int maxq = min(qt * 64 + 63, T_ - 1);
    int nkt  = maxq / 32 + 1;
    size_t kvbase = (size_t)(b * H_ + h) * T_ * D_;

    for (int kt = 0; kt < nkt; kt++) {
        int kbase = kt * 32;

#pragma unroll
        for (int u = 0; u < 8; u++) {
            int e4 = u * 64 + r;
            int j  = e4 >> 4;
            int d  = (e4 & 15) * 4;
            int kg = kbase + j;
            float4 kv = make_float4(0.f, 0.f, 0.f, 0.f);
            float4 vv = make_float4(0.f, 0.f, 0.f, 0.f);
            if (kg < T_) {
                kv = *(const float4*)&g_k[kvbase + (size_t)kg * D_ + d];
                vv = *(const float4*)&g_v[kvbase + (size_t)kg * D_ + d];
            }
            *(float4*)&Ks[j][d] = kv;
            *(float4*)&Vs[j][d] = vv;
        }
        __syncthreads();

        if (active) {
            float tmax = -1e30f;
#pragma unroll 1
            for (int j0 = 0; j0 < 32; j0 += 4) {
                float s0 = 0.f, s1 = 0.f, s2 = 0.f, s3 = 0.f;
#pragma unroll
                for (int d = 0; d < 64; d++) {
                    float qd = q[d];
                    s0 = fmaf(qd, Ks[j0 + 0][d], s0);
                    s1 = fmaf(qd, Ks[j0 + 1][d], s1);
                    s2 = fmaf(qd, Ks[j0 + 2][d], s2);
                    s3 = fmaf(qd, Ks[j0 + 3][d], s3);
                }
                if (kbase + j0 + 0 > qrow || kbase + j0 + 0 >= T_) s0 = -1e30f;
                if (kbase + j0 + 1 > qrow || kbase + j0 + 1 >= T_) s1 = -1e30f;
                if (kbase + j0 + 2 > qrow || kbase + j0 + 2 >= T_) s2 = -1e30f;
                if (kbase + j0 + 3 > qrow || kbase + j0 + 3 >= T_) s3 = -1e30f;
                Sb[j0 + 0][r] = s0;
                Sb[j0 + 1][r] = s1;
                Sb[j0 + 2][r] = s2;
                Sb[j0 + 3][r] = s3;
                tmax = fmaxf(tmax, fmaxf(fmaxf(s0, s1), fmaxf(s2, s3)));
            }

            float mnew = fmaxf(m, tmax);
            float f = __expf(m - mnew);
            l *= f;
#pragma unroll
            for (int d = 0; d < 64; d++) o[d] *= f;

#pragma unroll 1
            for (int j = 0; j < 32; j++) {
                float p = __expf(Sb[j][r] - mnew);
                l += p;
#pragma unroll
                for (int d = 0; d < 64; d++)
                    o[d] = fmaf(p, Vs[j][d], o[d]);
            }
            m = mnew;
        }
        __syncthreads();
    }

    if (active) {
        float inv = 1.f / l;
        float* yp = &g_y[((size_t)(b * T_) + qrow) * C_ + h * D_];
#pragma unroll
        for (int d = 0; d < 64; d += 4) {
            *(float4*)&yp[d] = make_float4(o[d] * inv, o[d + 1] * inv,
                                           o[d + 2] * inv, o[d + 3] * inv);
        }
    }
}

// ---------------------------------------------------------------------------
extern "C" void kernel_launch(void* const* d_in, const int* in_sizes, int n_in,
                              void* d_out, int out_size)
{
    const float* x      = (const float*)d_in[0];
    const float* W_attn = (const float*)d_in[2];
    const float* W_proj = (const float*)d_in[3];
    float* out = (float*)d_out;

    rope_table_kernel<<<T_, 32>>>();

    dim3 g_qkv(3072 / 128, (M_TOK + 127) / 128);   // 24 x 32
    gemm_tc<0><<<g_qkv, 256>>>(x, W_attn, nullptr, M_TOK, 3072, 1024);

    dim3 g_attn((T_ + 63) / 64, H_, B_);           // 16 x 16 x 4
    attn_kernel<<<g_attn, 64>>>();

    dim3 g_proj(1024 / 128, (M_TOK + 127) / 128);  // 8 x 32
    gemm_tc<1><<<g_proj, 256>>>(nullptr, W_proj, out, M_TOK, 1024, 1024);
}

// round 5
// speedup vs baseline: 2.8423x; 1.7501x over previous
#include <cuda_runtime.h>
#include <math.h>
#include <stdint.h>

#define B_    4
#define T_    1000
#define C_    1024
#define H_    16
#define D_    64
#define M_TOK (B_*T_)   // 4000

// Scratch (allocation-free: device globals)
__device__ float g_q[B_*H_*T_*D_];
__device__ float g_k[B_*H_*T_*D_];
__device__ float g_v[B_*H_*T_*D_];
__device__ float g_y[M_TOK*C_];
__device__ float g_cos[T_*(D_/2)];
__device__ float g_sin[T_*(D_/2)];

// ---------------------------------------------------------------------------
__device__ __forceinline__ uint32_t f2tf32(float x) {
    uint32_t u;
    asm("cvt.rna.tf32.f32 %0, %1;" : "=r"(u) : "f"(x));
    return u;
}

__device__ __forceinline__ void mma_tf32(float c[4],
                                         const uint32_t a[4],
                                         const uint32_t b[2]) {
    asm volatile(
        "mma.sync.aligned.m16n8k8.row.col.f32.tf32.tf32.f32 "
        "{%0,%1,%2,%3}, {%4,%5,%6,%7}, {%8,%9}, {%0,%1,%2,%3};"
        : "+f"(c[0]), "+f"(c[1]), "+f"(c[2]), "+f"(c[3])
        : "r"(a[0]), "r"(a[1]), "r"(a[2]), "r"(a[3]),
          "r"(b[0]), "r"(b[1]));
}

// ---------------------------------------------------------------------------
__global__ void rope_table_kernel() {
    int t = blockIdx.x;
    int i = threadIdx.x;
    float theta = (float)pow(10000.0, -(double)(2 * i) / 64.0);
    float ang = (float)t * theta;
    g_cos[t * 32 + i] = cosf(ang);
    g_sin[t * 32 + i] = sinf(ang);
}

// ---------------------------------------------------------------------------
// 128x128 tf32 tensor-core GEMM (unchanged from R3 — known good).
// ---------------------------------------------------------------------------
#define BK  16
#define LDS_ 136

template<int MODE>
__global__ void __launch_bounds__(256)
gemm_tc(const float* __restrict__ Ain, const float* __restrict__ Bw,
        float* __restrict__ Cout, int M, int N, int K)
{
    const float* A = (MODE == 1) ? (const float*)g_y : Ain;

    __shared__ uint32_t As[BK * LDS_];
    __shared__ uint32_t Bs[BK * LDS_];

    const int tid  = threadIdx.x;
    const int warp = tid >> 5;
    const int lane = tid & 31;
    const int g    = lane >> 2;
    const int tg   = lane & 3;
    const int wm   = warp >> 2;
    const int wn   = warp & 3;
    const int wmB  = wm * 64;
    const int wnB  = wn * 32;

    const int bm = blockIdx.y * 128;
    const int bn = blockIdx.x * 128;

    float acc[4][4][4];
#pragma unroll
    for (int mf = 0; mf < 4; mf++)
#pragma unroll
        for (int nf = 0; nf < 4; nf++)
#pragma unroll
            for (int i = 0; i < 4; i++) acc[mf][nf][i] = 0.f;

    const int aid0 = tid * 2;
    const int arow0 = aid0 >> 2,  akq0 = (aid0 & 3) * 4;
    const int arow1 = (aid0 + 1) >> 2, akq1 = ((aid0 + 1) & 3) * 4;
    const int brow0 = aid0 >> 5,  bc0  = (aid0 & 31) * 4;
    const int brow1 = (aid0 + 1) >> 5, bc1 = ((aid0 + 1) & 31) * 4;

    float4 pa0, pa1, pb0, pb1;
    {
        pa0 = make_float4(0.f, 0.f, 0.f, 0.f);
        pa1 = pa0;
        if (bm + arow0 < M) pa0 = *(const float4*)(A + (size_t)(bm + arow0) * K + akq0);
        if (bm + arow1 < M) pa1 = *(const float4*)(A + (size_t)(bm + arow1) * K + akq1);
        pb0 = *(const float4*)(Bw + (size_t)brow0 * N + bn + bc0);
        pb1 = *(const float4*)(Bw + (size_t)brow1 * N + bn + bc1);
    }

    const int nchunk = K / BK;
    for (int ch = 0; ch < nchunk; ch++) {
        As[(akq0 + 0) * LDS_ + arow0] = f2tf32(pa0.x);
        As[(akq0 + 1) * LDS_ + arow0] = f2tf32(pa0.y);
        As[(akq0 + 2) * LDS_ + arow0] = f2tf32(pa0.z);
        As[(akq0 + 3) * LDS_ + arow0] = f2tf32(pa0.w);
        As[(akq1 + 0) * LDS_ + arow1] = f2tf32(pa1.x);
        As[(akq1 + 1) * LDS_ + arow1] = f2tf32(pa1.y);
        As[(akq1 + 2) * LDS_ + arow1] = f2tf32(pa1.z);
        As[(akq1 + 3) * LDS_ + arow1] = f2tf32(pa1.w);
        {
            uint4 u0 = make_uint4(f2tf32(pb0.x), f2tf32(pb0.y), f2tf32(pb0.z), f2tf32(pb0.w));
            uint4 u1 = make_uint4(f2tf32(pb1.x), f2tf32(pb1.y), f2tf32(pb1.z), f2tf32(pb1.w));
            *(uint4*)&Bs[brow0 * LDS_ + bc0] = u0;
            *(uint4*)&Bs[brow1 * LDS_ + bc1] = u1;
        }
        __syncthreads();

        if (ch + 1 < nchunk) {
            const int k0 = (ch + 1) * BK;
            pa0 = make_float4(0.f, 0.f, 0.f, 0.f);
            pa1 = pa0;
            if (bm + arow0 < M) pa0 = *(const float4*)(A + (size_t)(bm + arow0) * K + k0 + akq0);
            if (bm + arow1 < M) pa1 = *(const float4*)(A + (size_t)(bm + arow1) * K + k0 + akq1);
            pb0 = *(const float4*)(Bw + (size_t)(k0 + brow0) * N + bn + bc0);
            pb1 = *(const float4*)(Bw + (size_t)(k0 + brow1) * N + bn + bc1);
        }

#pragma unroll
        for (int s = 0; s < 2; s++) {
            uint32_t afr[4][4], bfr[4][2];
            const int kr0 = (8 * s + tg) * LDS_;
            const int kr1 = (8 * s + tg + 4) * LDS_;
#pragma unroll
            for (int mf = 0; mf < 4; mf++) {
                int m0 = wmB + mf * 16 + g;
                afr[mf][0] = As[kr0 + m0];
                afr[mf][1] = As[kr0 + m0 + 8];
                afr[mf][2] = As[kr1 + m0];
                afr[mf][3] = As[kr1 + m0 + 8];
            }
#pragma unroll
            for (int nf = 0; nf < 4; nf++) {
                int n0 = wnB + nf * 8 + g;
                bfr[nf][0] = Bs[kr0 + n0];
                bfr[nf][1] = Bs[kr1 + n0];
            }
#pragma unroll
            for (int mf = 0; mf < 4; mf++)
#pragma unroll
                for (int nf = 0; nf < 4; nf++)
                    mma_tf32(acc[mf][nf], afr[mf], bfr[nf]);
        }
        __syncthreads();
    }

    if (MODE == 1) {
#pragma unroll
        for (int mf = 0; mf < 4; mf++) {
#pragma unroll
            for (int half = 0; half < 2; half++) {
                int gr = bm + wmB + mf * 16 + g + half * 8;
                if (gr >= M) continue;
#pragma unroll
                for (int nf = 0; nf < 4; nf++) {
                    int c = bn + wnB + nf * 8 + tg * 2;
                    *(float2*)&Cout[(size_t)gr * N + c] =
                        make_float2(acc[mf][nf][2 * half], acc[mf][nf][2 * half + 1]);
                }
            }
        }
    } else {
        int cwarp = bn + wnB;
        int which = cwarp >> 10;
        int h     = (cwarp & 1023) >> 6;
#pragma unroll
        for (int mf = 0; mf < 4; mf++) {
#pragma unroll
            for (int half = 0; half < 2; half++) {
                int gr = bm + wmB + mf * 16 + g + half * 8;
                if (gr >= M) continue;
                int b = gr / T_;
                int t = gr - b * T_;
                size_t rowbase = ((size_t)(b * H_ + h) * T_ + t) * D_;
#pragma unroll
                for (int nf = 0; nf < 4; nf++) {
                    int c     = bn + wnB + nf * 8 + tg * 2;
                    int dbase = c & 63;
                    float x0 = acc[mf][nf][2 * half];
                    float x1 = acc[mf][nf][2 * half + 1];
                    if (which == 2) {
                        *(float2*)&g_v[rowbase + dbase] = make_float2(x0, x1);
                    } else {
                        int pi = dbase >> 1;
                        float ct = g_cos[t * 32 + pi];
                        float st = g_sin[t * 32 + pi];
                        float* dst = (which == 0 ? g_q : g_k) + rowbase + dbase;
                        *(float2*)dst = make_float2(x0 * ct - x1 * st,
                                                    x1 * ct + x0 * st);
                    }
                }
            }
        }
    }
}

// ---------------------------------------------------------------------------
// Tensor-core flash attention (tf32 mma).
// Block = 128 threads (4 warps), q-tile = 64 (warp w owns q rows w*16..+15),
// kv-tile = 64. Phase A: S^T = K·Q^T. Phase B: O += P·V. Ps aliases Ks.
// ---------------------------------------------------------------------------
#define AP 68   // smem row pad (words)

__global__ void __launch_bounds__(128) attn_tc_kernel() {
    const int qt = (int)gridDim.x - 1 - (int)blockIdx.x;  // heavy tiles first
    const int h  = blockIdx.y;
    const int b  = blockIdx.z;

    __shared__ uint32_t SmA[64 * AP];   // K tile, then P tile (and Q staging)
    __shared__ uint32_t SmV[64 * AP];   // V tile

    const int tid  = threadIdx.x;
    const int warp = tid >> 5;
    const int lane = tid & 31;
    const int g    = lane >> 2;
    const int tg   = lane & 3;
    const int qw   = warp * 16;

    const size_t base = (size_t)(b * H_ + h) * T_ * D_;

    // ---- stage Q tile, extract Q^T B-fragments into registers ----
    float* Qs = (float*)SmA;
#pragma unroll
    for (int u = 0; u < 8; u++) {
        int i  = u * 128 + tid;
        int q  = i >> 4;
        int d4 = (i & 15) * 4;
        int row = min(qt * 64 + q, T_ - 1);
        *(float4*)&Qs[q * AP + d4] = *(const float4*)&g_q[base + (size_t)row * D_ + d4];
    }
    __syncthreads();

    uint32_t qb[8][2][2];
#pragma unroll
    for (int s = 0; s < 8; s++)
#pragma unroll
        for (int nf = 0; nf < 2; nf++) {
            int col = qw + nf * 8 + g;
            qb[s][nf][0] = f2tf32(Qs[col * AP + 8 * s + tg] * 0.125f);
            qb[s][nf][1] = f2tf32(Qs[col * AP + 8 * s + tg + 4] * 0.125f);
        }
    __syncthreads();

    // ---- persistent state ----
    float Ofr[8][4];
#pragma unroll
    for (int nf = 0; nf < 8; nf++)
#pragma unroll
        for (int i = 0; i < 4; i++) Ofr[nf][i] = 0.f;
    float mrun[4] = {-1e30f, -1e30f, -1e30f, -1e30f};
    float lrun[4] = {0.f, 0.f, 0.f, 0.f};

    const int srcl = (g >> 1) & 3;   // shfl source for col->row exchange

    for (int kt = 0; kt <= qt; kt++) {
        const int kb = kt * 64;

        // load K -> SmA (tf32), V -> SmV (tf32), natural [kv][d], coalesced
#pragma unroll
        for (int u = 0; u < 8; u++) {
            int i  = u * 128 + tid;
            int kv = i >> 4;
            int d4 = (i & 15) * 4;
            int row = min(kb + kv, T_ - 1);
            float4 kk = *(const float4*)&g_k[base + (size_t)row * D_ + d4];
            float4 vv = *(const float4*)&g_v[base + (size_t)row * D_ + d4];
            *(uint4*)&SmA[kv * AP + d4] =
                make_uint4(f2tf32(kk.x), f2tf32(kk.y), f2tf32(kk.z), f2tf32(kk.w));
            *(uint4*)&SmV[kv * AP + d4] =
                make_uint4(f2tf32(vv.x), f2tf32(vv.y), f2tf32(vv.z), f2tf32(vv.w));
        }
        __syncthreads();

        // ---- Phase A: S^T[kv][q] = K · Q^T ----
        float cS[4][2][4];
#pragma unroll
        for (int mf = 0; mf < 4; mf++)
#pragma unroll
            for (int nf = 0; nf < 2; nf++)
#pragma unroll
                for (int i = 0; i < 4; i++) cS[mf][nf][i] = 0.f;

#pragma unroll
        for (int s = 0; s < 8; s++) {
#pragma unroll
            for (int mf = 0; mf < 4; mf++) {
                uint32_t a[4];
                a[0] = SmA[(mf * 16 + g)     * AP + 8 * s + tg];
                a[1] = SmA[(mf * 16 + g + 8) * AP + 8 * s + tg];
                a[2] = SmA[(mf * 16 + g)     * AP + 8 * s + tg + 4];
                a[3] = SmA[(mf * 16 + g + 8) * AP + 8 * s + tg + 4];
                mma_tf32(cS[mf][0], a, qb[s][0]);
                mma_tf32(cS[mf][1], a, qb[s][1]);
            }
        }

        // causal mask (only the diagonal tile has masked entries)
        if (kt == qt) {
#pragma unroll
            for (int mf = 0; mf < 4; mf++)
#pragma unroll
                for (int nf = 0; nf < 2; nf++)
#pragma unroll
                    for (int i = 0; i < 4; i++) {
                        int kvg = kb + mf * 16 + g + (i >> 1) * 8;
                        int qg  = qt * 64 + qw + nf * 8 + 2 * tg + (i & 1);
                        if (kvg > qg) cS[mf][nf][i] = -1e30f;
                    }
        }

        // ---- softmax over q-columns ----
        float tmax[4];
#pragma unroll
        for (int nf = 0; nf < 2; nf++)
#pragma unroll
            for (int e = 0; e < 2; e++) {
                float v = -1e30f;
#pragma unroll
                for (int mf = 0; mf < 4; mf++)
                    v = fmaxf(v, fmaxf(cS[mf][nf][e], cS[mf][nf][2 + e]));
                tmax[nf * 2 + e] = v;
            }
#pragma unroll
        for (int st = 0; st < 4; st++) {
            tmax[st] = fmaxf(tmax[st], __shfl_xor_sync(0xffffffffu, tmax[st], 4));
            tmax[st] = fmaxf(tmax[st], __shfl_xor_sync(0xffffffffu, tmax[st], 8));
            tmax[st] = fmaxf(tmax[st], __shfl_xor_sync(0xffffffffu, tmax[st], 16));
        }
        float fst[4];
#pragma unroll
        for (int st = 0; st < 4; st++) {
            float mnew = fmaxf(mrun[st], tmax[st]);
            fst[st] = __expf(mrun[st] - mnew);
            mrun[st] = mnew;
            lrun[st] *= fst[st];
        }

        // P = exp(S - m), accumulate l partials (per-thread; g-reduced at end)
#pragma unroll
        for (int mf = 0; mf < 4; mf++)
#pragma unroll
            for (int nf = 0; nf < 2; nf++)
#pragma unroll
                for (int i = 0; i < 4; i++) {
                    float p = __expf(cS[mf][nf][i] - mrun[nf * 2 + (i & 1)]);
                    cS[mf][nf][i] = p;
                    lrun[nf * 2 + (i & 1)] += p;
                }

        __syncthreads();   // all warps done reading K tile (SmA) in phase A

        // store P^T -> Ps[q][kv]  (scatter: bank = 8*tg+g, conflict-free)
        uint32_t* Ps = SmA;
#pragma unroll
        for (int mf = 0; mf < 4; mf++)
#pragma unroll
            for (int nf = 0; nf < 2; nf++)
#pragma unroll
                for (int i = 0; i < 4; i++) {
                    int qloc = qw + nf * 8 + 2 * tg + (i & 1);
                    int kv   = mf * 16 + g + (i >> 1) * 8;
                    Ps[qloc * AP + kv] = f2tf32(cS[mf][nf][i]);
                }
        __syncwarp();

        // rescale O by f (exchange col-state -> row-state, 4 shfls)
        {
            float f0 = __shfl_sync(0xffffffffu, fst[0], srcl);
            float f1 = __shfl_sync(0xffffffffu, fst[1], srcl);
            float f2 = __shfl_sync(0xffffffffu, fst[2], srcl);
            float f3 = __shfl_sync(0xffffffffu, fst[3], srcl);
            float fr0 = (g & 1) ? f1 : f0;
            float fr1 = (g & 1) ? f3 : f2;
#pragma unroll
            for (int nf = 0; nf < 8; nf++) {
                Ofr[nf][0] *= fr0;
                Ofr[nf][1] *= fr0;
                Ofr[nf][2] *= fr1;
                Ofr[nf][3] *= fr1;
            }
        }

        // ---- Phase B: O[q][d] += P · V ----
#pragma unroll
        for (int s = 0; s < 8; s++) {
            uint32_t a[4];
            a[0] = Ps[(qw + g)     * AP + 8 * s + tg];
            a[1] = Ps[(qw + g + 8) * AP + 8 * s + tg];
            a[2] = Ps[(qw + g)     * AP + 8 * s + tg + 4];
            a[3] = Ps[(qw + g + 8) * AP + 8 * s + tg + 4];
#pragma unroll
            for (int nf = 0; nf < 8; nf++) {
                uint32_t bb[2];
                bb[0] = SmV[(8 * s + tg)     * AP + nf * 8 + g];
                bb[1] = SmV[(8 * s + tg + 4) * AP + nf * 8 + g];
                mma_tf32(Ofr[nf], a, bb);
            }
        }
        __syncthreads();   // before next tile overwrites SmA/SmV
    }

    // ---- FIX: reduce l partials across the 8 g-lanes of each q-column ----
#pragma unroll
    for (int st = 0; st < 4; st++) {
        lrun[st] += __shfl_xor_sync(0xffffffffu, lrun[st], 4);
        lrun[st] += __shfl_xor_sync(0xffffffffu, lrun[st], 8);
        lrun[st] += __shfl_xor_sync(0xffffffffu, lrun[st], 16);
    }

    // ---- final: exchange l to row ownership, normalize, write ----
    float l0 = __shfl_sync(0xffffffffu, lrun[0], srcl);
    float l1 = __shfl_sync(0xffffffffu, lrun[1], srcl);
    float l2 = __shfl_sync(0xffffffffu, lrun[2], srcl);
    float l3 = __shfl_sync(0xffffffffu, lrun[3], srcl);
    float lr0 = (g & 1) ? l1 : l0;
    float lr1 = (g & 1) ? l3 : l2;
    float inv0 = 1.f / lr0;
    float inv1 = 1.f / lr1;

    int qg0 = qt * 64 + qw + g;
    int qg1 = qg0 + 8;
    if (qg0 < T_) {
        float* yp = &g_y[((size_t)(b * T_) + qg0) * C_ + h * D_];
#pragma unroll
        for (int nf = 0; nf < 8; nf++)
            *(float2*)&yp[nf * 8 + 2 * tg] =
                make_float2(Ofr[nf][0] * inv0, Ofr[nf][1] * inv0);
    }
    if (qg1 < T_) {
        float* yp = &g_y[((size_t)(b * T_) + qg1) * C_ + h * D_];
#pragma unroll
        for (int nf = 0; nf < 8; nf++)
            *(float2*)&yp[nf * 8 + 2 * tg] =
                make_float2(Ofr[nf][2] * inv1, Ofr[nf][3] * inv1);
    }
}

// ---------------------------------------------------------------------------
extern "C" void kernel_launch(void* const* d_in, const int* in_sizes, int n_in,
                              void* d_out, int out_size)
{
    const float* x      = (const float*)d_in[0];
    const float* W_attn = (const float*)d_in[2];
    const float* W_proj = (const float*)d_in[3];
    float* out = (float*)d_out;

    rope_table_kernel<<<T_, 32>>>();

    dim3 g_qkv(3072 / 128, (M_TOK + 127) / 128);   // 24 x 32
    gemm_tc<0><<<g_qkv, 256>>>(x, W_attn, nullptr, M_TOK, 3072, 1024);

    dim3 g_attn((T_ + 63) / 64, H_, B_);           // 16 x 16 x 4
    attn_tc_kernel<<<g_attn, 128>>>();

    dim3 g_proj(1024 / 128, (M_TOK + 127) / 128);  // 8 x 32
    gemm_tc<1><<<g_proj, 256>>>(nullptr, W_proj, out, M_TOK, 1024, 1024);
}

// round 6
// speedup vs baseline: 3.0994x; 1.0905x over previous
#include <cuda_runtime.h>
#include <math.h>
#include <stdint.h>

#define B_    4
#define T_    1000
#define C_    1024
#define H_    16
#define D_    64
#define M_TOK (B_*T_)   // 4000

// Scratch (allocation-free: device globals)
__device__ float g_q[B_*H_*T_*D_];
__device__ float g_k[B_*H_*T_*D_];
__device__ float g_v[B_*H_*T_*D_];
__device__ float g_y[M_TOK*C_];
__device__ float g_cos[T_*(D_/2)];
__device__ float g_sin[T_*(D_/2)];

// ---------------------------------------------------------------------------
__device__ __forceinline__ uint32_t f2tf32(float x) {
    uint32_t u;
    asm("cvt.rna.tf32.f32 %0, %1;" : "=r"(u) : "f"(x));
    return u;
}

__device__ __forceinline__ void mma_tf32(float c[4],
                                         const uint32_t a[4],
                                         const uint32_t b[2]) {
    asm volatile(
        "mma.sync.aligned.m16n8k8.row.col.f32.tf32.tf32.f32 "
        "{%0,%1,%2,%3}, {%4,%5,%6,%7}, {%8,%9}, {%0,%1,%2,%3};"
        : "+f"(c[0]), "+f"(c[1]), "+f"(c[2]), "+f"(c[3])
        : "r"(a[0]), "r"(a[1]), "r"(a[2]), "r"(a[3]),
          "r"(b[0]), "r"(b[1]));
}

// ---------------------------------------------------------------------------
__global__ void rope_table_kernel() {
    int t = blockIdx.x;
    int i = threadIdx.x;
    float theta = (float)pow(10000.0, -(double)(2 * i) / 64.0);
    float ang = (float)t * theta;
    g_cos[t * 32 + i] = cosf(ang);
    g_sin[t * 32 + i] = sinf(ang);
}

// ---------------------------------------------------------------------------
// 128x128 tf32 tensor-core GEMM, double-buffered smem, 1 sync per K-chunk.
// 256 threads = 8 warps (2m x 4n), each warp 64x32 via 4x4 m16n8k8 frags.
// MODE 0: C = x @ W_attn, epilogue fuses RoPE, scatters Q/K/V [B,H,T,D].
// MODE 1: C = g_y @ W_proj -> Cout row-major.
// ---------------------------------------------------------------------------
#define BK  16
#define LDS_ 136

template<int MODE>
__global__ void __launch_bounds__(256, 2)
gemm_tc(const float* __restrict__ Ain, const float* __restrict__ Bw,
        float* __restrict__ Cout, int M, int N, int K)
{
    const float* A = (MODE == 1) ? (const float*)g_y : Ain;

    __shared__ uint32_t As[2][BK * LDS_];
    __shared__ uint32_t Bs[2][BK * LDS_];

    const int tid  = threadIdx.x;
    const int warp = tid >> 5;
    const int lane = tid & 31;
    const int g    = lane >> 2;
    const int tg   = lane & 3;
    const int wm   = warp >> 2;
    const int wn   = warp & 3;
    const int wmB  = wm * 64;
    const int wnB  = wn * 32;

    const int bm = blockIdx.y * 128;
    const int bn = blockIdx.x * 128;

    float acc[4][4][4];
#pragma unroll
    for (int mf = 0; mf < 4; mf++)
#pragma unroll
        for (int nf = 0; nf < 4; nf++)
#pragma unroll
            for (int i = 0; i < 4; i++) acc[mf][nf][i] = 0.f;

    const int aid0 = tid * 2;
    const int arow0 = aid0 >> 2,  akq0 = (aid0 & 3) * 4;
    const int arow1 = (aid0 + 1) >> 2, akq1 = ((aid0 + 1) & 3) * 4;
    const int brow0 = aid0 >> 5,  bc0  = (aid0 & 31) * 4;
    const int brow1 = (aid0 + 1) >> 5, bc1 = ((aid0 + 1) & 31) * 4;

    float4 pa0, pa1, pb0, pb1;

    // prologue: load chunk 0 and store into stage 0
    {
        pa0 = make_float4(0.f, 0.f, 0.f, 0.f);
        pa1 = pa0;
        if (bm + arow0 < M) pa0 = *(const float4*)(A + (size_t)(bm + arow0) * K + akq0);
        if (bm + arow1 < M) pa1 = *(const float4*)(A + (size_t)(bm + arow1) * K + akq1);
        pb0 = *(const float4*)(Bw + (size_t)brow0 * N + bn + bc0);
        pb1 = *(const float4*)(Bw + (size_t)brow1 * N + bn + bc1);

        As[0][(akq0 + 0) * LDS_ + arow0] = f2tf32(pa0.x);
        As[0][(akq0 + 1) * LDS_ + arow0] = f2tf32(pa0.y);
        As[0][(akq0 + 2) * LDS_ + arow0] = f2tf32(pa0.z);
        As[0][(akq0 + 3) * LDS_ + arow0] = f2tf32(pa0.w);
        As[0][(akq1 + 0) * LDS_ + arow1] = f2tf32(pa1.x);
        As[0][(akq1 + 1) * LDS_ + arow1] = f2tf32(pa1.y);
        As[0][(akq1 + 2) * LDS_ + arow1] = f2tf32(pa1.z);
        As[0][(akq1 + 3) * LDS_ + arow1] = f2tf32(pa1.w);
        uint4 u0 = make_uint4(f2tf32(pb0.x), f2tf32(pb0.y), f2tf32(pb0.z), f2tf32(pb0.w));
        uint4 u1 = make_uint4(f2tf32(pb1.x), f2tf32(pb1.y), f2tf32(pb1.z), f2tf32(pb1.w));
        *(uint4*)&Bs[0][brow0 * LDS_ + bc0] = u0;
        *(uint4*)&Bs[0][brow1 * LDS_ + bc1] = u1;
    }
    __syncthreads();

    const int nchunk = K / BK;
    for (int ch = 0; ch < nchunk; ch++) {
        const int cur = ch & 1;
        const int nxt = cur ^ 1;
        const bool have_next = (ch + 1 < nchunk);

        // issue next-chunk global loads first (latency hidden by compute)
        if (have_next) {
            const int k0 = (ch + 1) * BK;
            pa0 = make_float4(0.f, 0.f, 0.f, 0.f);
            pa1 = pa0;
            if (bm + arow0 < M) pa0 = *(const float4*)(A + (size_t)(bm + arow0) * K + k0 + akq0);
            if (bm + arow1 < M) pa1 = *(const float4*)(A + (size_t)(bm + arow1) * K + k0 + akq1);
            pb0 = *(const float4*)(Bw + (size_t)(k0 + brow0) * N + bn + bc0);
            pb1 = *(const float4*)(Bw + (size_t)(k0 + brow1) * N + bn + bc1);
        }

        // compute current stage: 2 k-steps of 8
#pragma unroll
        for (int s = 0; s < 2; s++) {
            uint32_t afr[4][4], bfr[4][2];
            const int kr0 = (8 * s + tg) * LDS_;
            const int kr1 = (8 * s + tg + 4) * LDS_;
#pragma unroll
            for (int mf = 0; mf < 4; mf++) {
                int m0 = wmB + mf * 16 + g;
                afr[mf][0] = As[cur][kr0 + m0];
                afr[mf][1] = As[cur][kr0 + m0 + 8];
                afr[mf][2] = As[cur][kr1 + m0];
                afr[mf][3] = As[cur][kr1 + m0 + 8];
            }
#pragma unroll
            for (int nf = 0; nf < 4; nf++) {
                int n0 = wnB + nf * 8 + g;
                bfr[nf][0] = Bs[cur][kr0 + n0];
                bfr[nf][1] = Bs[cur][kr1 + n0];
            }
#pragma unroll
            for (int mf = 0; mf < 4; mf++)
#pragma unroll
                for (int nf = 0; nf < 4; nf++)
                    mma_tf32(acc[mf][nf], afr[mf], bfr[nf]);
        }

        // store prefetched chunk into the other stage
        if (have_next) {
            As[nxt][(akq0 + 0) * LDS_ + arow0] = f2tf32(pa0.x);
            As[nxt][(akq0 + 1) * LDS_ + arow0] = f2tf32(pa0.y);
            As[nxt][(akq0 + 2) * LDS_ + arow0] = f2tf32(pa0.z);
            As[nxt][(akq0 + 3) * LDS_ + arow0] = f2tf32(pa0.w);
            As[nxt][(akq1 + 0) * LDS_ + arow1] = f2tf32(pa1.x);
            As[nxt][(akq1 + 1) * LDS_ + arow1] = f2tf32(pa1.y);
            As[nxt][(akq1 + 2) * LDS_ + arow1] = f2tf32(pa1.z);
            As[nxt][(akq1 + 3) * LDS_ + arow1] = f2tf32(pa1.w);
            uint4 u0 = make_uint4(f2tf32(pb0.x), f2tf32(pb0.y), f2tf32(pb0.z), f2tf32(pb0.w));
            uint4 u1 = make_uint4(f2tf32(pb1.x), f2tf32(pb1.y), f2tf32(pb1.z), f2tf32(pb1.w));
            *(uint4*)&Bs[nxt][brow0 * LDS_ + bc0] = u0;
            *(uint4*)&Bs[nxt][brow1 * LDS_ + bc1] = u1;
            __syncthreads();
        }
    }

    // ---------------- epilogue ----------------
    if (MODE == 1) {
#pragma unroll
        for (int mf = 0; mf < 4; mf++) {
#pragma unroll
            for (int half = 0; half < 2; half++) {
                int gr = bm + wmB + mf * 16 + g + half * 8;
                if (gr >= M) continue;
#pragma unroll
                for (int nf = 0; nf < 4; nf++) {
                    int c = bn + wnB + nf * 8 + tg * 2;
                    *(float2*)&Cout[(size_t)gr * N + c] =
                        make_float2(acc[mf][nf][2 * half], acc[mf][nf][2 * half + 1]);
                }
            }
        }
    } else {
        int cwarp = bn + wnB;
        int which = cwarp >> 10;
        int h     = (cwarp & 1023) >> 6;
#pragma unroll
        for (int mf = 0; mf < 4; mf++) {
#pragma unroll
            for (int half = 0; half < 2; half++) {
                int gr = bm + wmB + mf * 16 + g + half * 8;
                if (gr >= M) continue;
                int b = gr / T_;
                int t = gr - b * T_;
                size_t rowbase = ((size_t)(b * H_ + h) * T_ + t) * D_;
#pragma unroll
                for (int nf = 0; nf < 4; nf++) {
                    int c     = bn + wnB + nf * 8 + tg * 2;
                    int dbase = c & 63;
                    float x0 = acc[mf][nf][2 * half];
                    float x1 = acc[mf][nf][2 * half + 1];
                    if (which == 2) {
                        *(float2*)&g_v[rowbase + dbase] = make_float2(x0, x1);
                    } else {
                        int pi = dbase >> 1;
                        float ct = g_cos[t * 32 + pi];
                        float st = g_sin[t * 32 + pi];
                        float* dst = (which == 0 ? g_q : g_k) + rowbase + dbase;
                        *(float2*)dst = make_float2(x0 * ct - x1 * st,
                                                    x1 * ct + x0 * st);
                    }
                }
            }
        }
    }
}

// ---------------------------------------------------------------------------
// Tensor-core flash attention (tf32 mma) — unchanged from R5 (known good).
// ---------------------------------------------------------------------------
#define AP 68   // smem row pad (words)

__global__ void __launch_bounds__(128) attn_tc_kernel() {
    const int qt = (int)gridDim.x - 1 - (int)blockIdx.x;  // heavy tiles first
    const int h  = blockIdx.y;
    const int b  = blockIdx.z;

    __shared__ uint32_t SmA[64 * AP];   // K tile, then P tile (and Q staging)
    __shared__ uint32_t SmV[64 * AP];   // V tile

    const int tid  = threadIdx.x;
    const int warp = tid >> 5;
    const int lane = tid & 31;
    const int g    = lane >> 2;
    const int tg   = lane & 3;
    const int qw   = warp * 16;

    const size_t base = (size_t)(b * H_ + h) * T_ * D_;

    // ---- stage Q tile, extract Q^T B-fragments into registers ----
    float* Qs = (float*)SmA;
#pragma unroll
    for (int u = 0; u < 8; u++) {
        int i  = u * 128 + tid;
        int q  = i >> 4;
        int d4 = (i & 15) * 4;
        int row = min(qt * 64 + q, T_ - 1);
        *(float4*)&Qs[q * AP + d4] = *(const float4*)&g_q[base + (size_t)row * D_ + d4];
    }
    __syncthreads();

    uint32_t qb[8][2][2];
#pragma unroll
    for (int s = 0; s < 8; s++)
#pragma unroll
        for (int nf = 0; nf < 2; nf++) {
            int col = qw + nf * 8 + g;
            qb[s][nf][0] = f2tf32(Qs[col * AP + 8 * s + tg] * 0.125f);
            qb[s][nf][1] = f2tf32(Qs[col * AP + 8 * s + tg + 4] * 0.125f);
        }
    __syncthreads();

    // ---- persistent state ----
    float Ofr[8][4];
#pragma unroll
    for (int nf = 0; nf < 8; nf++)
#pragma unroll
        for (int i = 0; i < 4; i++) Ofr[nf][i] = 0.f;
    float mrun[4] = {-1e30f, -1e30f, -1e30f, -1e30f};
    float lrun[4] = {0.f, 0.f, 0.f, 0.f};

    const int srcl = (g >> 1) & 3;   // shfl source for col->row exchange

    for (int kt = 0; kt <= qt; kt++) {
        const int kb = kt * 64;

#pragma unroll
        for (int u = 0; u < 8; u++) {
            int i  = u * 128 + tid;
            int kv = i >> 4;
            int d4 = (i & 15) * 4;
            int row = min(kb + kv, T_ - 1);
            float4 kk = *(const float4*)&g_k[base + (size_t)row * D_ + d4];
            float4 vv = *(const float4*)&g_v[base + (size_t)row * D_ + d4];
            *(uint4*)&SmA[kv * AP + d4] =
                make_uint4(f2tf32(kk.x), f2tf32(kk.y), f2tf32(kk.z), f2tf32(kk.w));
            *(uint4*)&SmV[kv * AP + d4] =
                make_uint4(f2tf32(vv.x), f2tf32(vv.y), f2tf32(vv.z), f2tf32(vv.w));
        }
        __syncthreads();

        // ---- Phase A: S^T[kv][q] = K · Q^T ----
        float cS[4][2][4];
#pragma unroll
        for (int mf = 0; mf < 4; mf++)
#pragma unroll
            for (int nf = 0; nf < 2; nf++)
#pragma unroll
                for (int i = 0; i < 4; i++) cS[mf][nf][i] = 0.f;

#pragma unroll
        for (int s = 0; s < 8; s++) {
#pragma unroll
            for (int mf = 0; mf < 4; mf++) {
                uint32_t a[4];
                a[0] = SmA[(mf * 16 + g)     * AP + 8 * s + tg];
                a[1] = SmA[(mf * 16 + g + 8) * AP + 8 * s + tg];
                a[2] = SmA[(mf * 16 + g)     * AP + 8 * s + tg + 4];
                a[3] = SmA[(mf * 16 + g + 8) * AP + 8 * s + tg + 4];
                mma_tf32(cS[mf][0], a, qb[s][0]);
                mma_tf32(cS[mf][1], a, qb[s][1]);
            }
        }

        // causal mask (only the diagonal tile has masked entries)
        if (kt == qt) {
#pragma unroll
            for (int mf = 0; mf < 4; mf++)
#pragma unroll
                for (int nf = 0; nf < 2; nf++)
#pragma unroll
                    for (int i = 0; i < 4; i++) {
                        int kvg = kb + mf * 16 + g + (i >> 1) * 8;
                        int qg  = qt * 64 + qw + nf * 8 + 2 * tg + (i & 1);
                        if (kvg > qg) cS[mf][nf][i] = -1e30f;
                    }
        }

        // ---- softmax over q-columns ----
        float tmax[4];
#pragma unroll
        for (int nf = 0; nf < 2; nf++)
#pragma unroll
            for (int e = 0; e < 2; e++) {
                float v = -1e30f;
#pragma unroll
                for (int mf = 0; mf < 4; mf++)
                    v = fmaxf(v, fmaxf(cS[mf][nf][e], cS[mf][nf][2 + e]));
                tmax[nf * 2 + e] = v;
            }
#pragma unroll
        for (int st = 0; st < 4; st++) {
            tmax[st] = fmaxf(tmax[st], __shfl_xor_sync(0xffffffffu, tmax[st], 4));
            tmax[st] = fmaxf(tmax[st], __shfl_xor_sync(0xffffffffu, tmax[st], 8));
            tmax[st] = fmaxf(tmax[st], __shfl_xor_sync(0xffffffffu, tmax[st], 16));
        }
        float fst[4];
#pragma unroll
        for (int st = 0; st < 4; st++) {
            float mnew = fmaxf(mrun[st], tmax[st]);
            fst[st] = __expf(mrun[st] - mnew);
            mrun[st] = mnew;
            lrun[st] *= fst[st];
        }

        // P = exp(S - m), accumulate l partials (per-thread; g-reduced at end)
#pragma unroll
        for (int mf = 0; mf < 4; mf++)
#pragma unroll
            for (int nf = 0; nf < 2; nf++)
#pragma unroll
                for (int i = 0; i < 4; i++) {
                    float p = __expf(cS[mf][nf][i] - mrun[nf * 2 + (i & 1)]);
                    cS[mf][nf][i] = p;
                    lrun[nf * 2 + (i & 1)] += p;
                }

        __syncthreads();   // all warps done reading K tile (SmA) in phase A

        // store P^T -> Ps[q][kv]  (scatter: bank = 8*tg+g, conflict-free)
        uint32_t* Ps = SmA;
#pragma unroll
        for (int mf = 0; mf < 4; mf++)
#pragma unroll
            for (int nf = 0; nf < 2; nf++)
#pragma unroll
                for (int i = 0; i < 4; i++) {
                    int qloc = qw + nf * 8 + 2 * tg + (i & 1);
                    int kv   = mf * 16 + g + (i >> 1) * 8;
                    Ps[qloc * AP + kv] = f2tf32(cS[mf][nf][i]);
                }
        __syncwarp();

        // rescale O by f (exchange col-state -> row-state, 4 shfls)
        {
            float f0 = __shfl_sync(0xffffffffu, fst[0], srcl);
            float f1 = __shfl_sync(0xffffffffu, fst[1], srcl);
            float f2 = __shfl_sync(0xffffffffu, fst[2], srcl);
            float f3 = __shfl_sync(0xffffffffu, fst[3], srcl);
            float fr0 = (g & 1) ? f1 : f0;
            float fr1 = (g & 1) ? f3 : f2;
#pragma unroll
            for (int nf = 0; nf < 8; nf++) {
                Ofr[nf][0] *= fr0;
                Ofr[nf][1] *= fr0;
                Ofr[nf][2] *= fr1;
                Ofr[nf][3] *= fr1;
            }
        }

        // ---- Phase B: O[q][d] += P · V ----
#pragma unroll
        for (int s = 0; s < 8; s++) {
            uint32_t a[4];
            a[0] = Ps[(qw + g)     * AP + 8 * s + tg];
            a[1] = Ps[(qw + g + 8) * AP + 8 * s + tg];
            a[2] = Ps[(qw + g)     * AP + 8 * s + tg + 4];
            a[3] = Ps[(qw + g + 8) * AP + 8 * s + tg + 4];
#pragma unroll
            for (int nf = 0; nf < 8; nf++) {
                uint32_t bb[2];
                bb[0] = SmV[(8 * s + tg)     * AP + nf * 8 + g];
                bb[1] = SmV[(8 * s + tg + 4) * AP + nf * 8 + g];
                mma_tf32(Ofr[nf], a, bb);
            }
        }
        __syncthreads();   // before next tile overwrites SmA/SmV
    }

    // reduce l partials across the 8 g-lanes of each q-column
#pragma unroll
    for (int st = 0; st < 4; st++) {
        lrun[st] += __shfl_xor_sync(0xffffffffu, lrun[st], 4);
        lrun[st] += __shfl_xor_sync(0xffffffffu, lrun[st], 8);
        lrun[st] += __shfl_xor_sync(0xffffffffu, lrun[st], 16);
    }

    // ---- final: exchange l to row ownership, normalize, write ----
    float l0 = __shfl_sync(0xffffffffu, lrun[0], srcl);
    float l1 = __shfl_sync(0xffffffffu, lrun[1], srcl);
    float l2 = __shfl_sync(0xffffffffu, lrun[2], srcl);
    float l3 = __shfl_sync(0xffffffffu, lrun[3], srcl);
    float lr0 = (g & 1) ? l1 : l0;
    float lr1 = (g & 1) ? l3 : l2;
    float inv0 = 1.f / lr0;
    float inv1 = 1.f / lr1;

    int qg0 = qt * 64 + qw + g;
    int qg1 = qg0 + 8;
    if (qg0 < T_) {
        float* yp = &g_y[((size_t)(b * T_) + qg0) * C_ + h * D_];
#pragma unroll
        for (int nf = 0; nf < 8; nf++)
            *(float2*)&yp[nf * 8 + 2 * tg] =
                make_float2(Ofr[nf][0] * inv0, Ofr[nf][1] * inv0);
    }
    if (qg1 < T_) {
        float* yp = &g_y[((size_t)(b * T_) + qg1) * C_ + h * D_];
#pragma unroll
        for (int nf = 0; nf < 8; nf++)
            *(float2*)&yp[nf * 8 + 2 * tg] =
                make_float2(Ofr[nf][2] * inv1, Ofr[nf][3] * inv1);
    }
}

// ---------------------------------------------------------------------------
extern "C" void kernel_launch(void* const* d_in, const int* in_sizes, int n_in,
                              void* d_out, int out_size)
{
    const float* x      = (const float*)d_in[0];
    const float* W_attn = (const float*)d_in[2];
    const float* W_proj = (const float*)d_in[3];
    float* out = (float*)d_out;

    rope_table_kernel<<<T_, 32>>>();

    dim3 g_qkv(3072 / 128, (M_TOK + 127) / 128);   // 24 x 32
    gemm_tc<0><<<g_qkv, 256>>>(x, W_attn, nullptr, M_TOK, 3072, 1024);

    dim3 g_attn((T_ + 63) / 64, H_, B_);           // 16 x 16 x 4
    attn_tc_kernel<<<g_attn, 128>>>();

    dim3 g_proj(1024 / 128, (M_TOK + 127) / 128);  // 8 x 32
    gemm_tc<1><<<g_proj, 256>>>(nullptr, W_proj, out, M_TOK, 1024, 1024);
}